// round 16
// baseline (speedup 1.0000x reference)
#include <cuda_runtime.h>
#include <cuda_bf16.h>
#include <cstdint>
#include <stdint.h>
#include <math.h>

#define BB 2048
#define LL 50
#define DD 128
#define VO 50001
#define NPAD 50048           // 391 * 128
#define BLr (BB*LL)          // 102400 rows

typedef unsigned long long ULL;
typedef __nv_bfloat16 bf16;

// ---------------- f32x2 helpers ----------------
__device__ __forceinline__ ULL pk2(float lo, float hi) {
    ULL r; asm("mov.b64 %0,{%1,%2};" : "=l"(r) : "f"(lo), "f"(hi)); return r;
}
__device__ __forceinline__ void fma2(ULL& d, ULL a, ULL b) {
    asm("fma.rn.f32x2 %0,%1,%2,%0;" : "+l"(d) : "l"(a), "l"(b));
}
__device__ __forceinline__ float2 upk2(ULL v) {
    float2 r; asm("mov.b64 {%0,%1},%2;" : "=f"(r.x), "=f"(r.y) : "l"(v)); return r;
}

// ---------------- mma.sync helpers ----------------
__device__ __forceinline__ uint32_t smem_u32(const void* p) {
    uint32_t a; asm("{ .reg .u64 t; cvta.to.shared.u64 t, %1; cvt.u32.u64 %0, t; }" : "=r"(a) : "l"(p));
    return a;
}
__device__ __forceinline__ void ldsm4(uint32_t* r, uint32_t addr) {
    asm volatile("ldmatrix.sync.aligned.m8n8.x4.shared.b16 {%0,%1,%2,%3}, [%4];"
        : "=r"(r[0]), "=r"(r[1]), "=r"(r[2]), "=r"(r[3]) : "r"(addr));
}
__device__ __forceinline__ void ldsm2(uint32_t* r, uint32_t addr) {
    asm volatile("ldmatrix.sync.aligned.m8n8.x2.shared.b16 {%0,%1}, [%2];"
        : "=r"(r[0]), "=r"(r[1]) : "r"(addr));
}
__device__ __forceinline__ void mma16816(float* c, const uint32_t* a, const uint32_t* b) {
    asm volatile("mma.sync.aligned.m16n8k16.row.col.f32.bf16.bf16.f32 "
        "{%0,%1,%2,%3}, {%4,%5,%6,%7}, {%8,%9}, {%0,%1,%2,%3};"
        : "+f"(c[0]), "+f"(c[1]), "+f"(c[2]), "+f"(c[3])
        : "r"(a[0]), "r"(a[1]), "r"(a[2]), "r"(a[3]), "r"(b[0]), "r"(b[1]));
}
__device__ __forceinline__ void split1(float v, bf16& h, bf16& l) {
    h = __float2bfloat16(v);
    l = __float2bfloat16(v - __bfloat162float(h));
}

// ---------------- scratch ----------------
__device__ bf16  g_xHi[(size_t)BLr*DD];
__device__ bf16  g_xLo[(size_t)BLr*DD];
__device__ float g_gi[(size_t)BLr*3*DD];
__device__ float g_hseq[(size_t)BLr*DD];
__device__ float g_hpos[(size_t)BLr*DD];
__device__ bf16  g_hposHi[(size_t)BLr*DD];
__device__ bf16  g_hposLo[(size_t)BLr*DD];
__device__ float g_qkv[(size_t)BLr*3*DD];
__device__ bf16  g_attnoHi[(size_t)BLr*DD];
__device__ bf16  g_attnoLo[(size_t)BLr*DD];
__device__ float g_oproj[(size_t)BLr*DD];
__device__ float g_h1[(size_t)BLr*DD];
__device__ bf16  g_h1Hi[(size_t)BLr*DD];
__device__ bf16  g_h1Lo[(size_t)BLr*DD];
__device__ bf16  g_ffHi[(size_t)BLr*4*DD];
__device__ bf16  g_ffLo[(size_t)BLr*4*DD];
__device__ float g_ff2[(size_t)BLr*DD];
__device__ float g_hattn[(size_t)BLr*DD];
__device__ float g_short[(size_t)BB*DD];
__device__ float g_WT[(size_t)DD*3*DD];
__device__ bf16  g_wHi[(size_t)NPAD*DD];
__device__ bf16  g_wLo[(size_t)NPAD*DD];
__device__ bf16  g_aHi[(size_t)BB*DD];
__device__ bf16  g_aLo[(size_t)BB*DD];
// weight splits
__device__ bf16  g_wihHi[384*DD],  g_wihLo[384*DD];
__device__ bf16  g_inpHi[384*DD],  g_inpLo[384*DD];
__device__ bf16  g_opHi[DD*DD],    g_opLo[DD*DD];
__device__ bf16  g_f1Hi[512*DD],   g_f1Lo[512*DD];
__device__ bf16  g_f2Hi[DD*512],   g_f2Lo[DD*512];

// ---------------- small elementwise kernels ----------------
__global__ void embed_hilo_kernel(const int* __restrict__ seq, const float* __restrict__ emb,
                                  bf16* __restrict__ xh, bf16* __restrict__ xl) {
    int idx = blockIdx.x*blockDim.x + threadIdx.x;
    if (idx >= BLr*DD) return;
    int bl = idx >> 7; int d = idx & 127;
    int s = seq[bl];
    float v = (s > 0) ? emb[(size_t)s*DD + d] : 0.f;
    split1(v, xh[idx], xl[idx]);
}

__global__ void transpose_whh(const float* __restrict__ whh, float* __restrict__ WT) {
    int idx = blockIdx.x*blockDim.x + threadIdx.x;
    if (idx >= 3*DD*DD) return;
    int c = idx / DD, k = idx % DD;
    WT[k*(3*DD) + c] = whh[idx];
}

__global__ void split_w_kernel(const float* __restrict__ src, bf16* __restrict__ hi,
                               bf16* __restrict__ lo, int n) {
    int idx = blockIdx.x*blockDim.x + threadIdx.x;
    if (idx >= n) return;
    split1(src[idx], hi[idx], lo[idx]);
}

__global__ void split_emb_kernel(const float* __restrict__ emb,
                                 bf16* __restrict__ hi, bf16* __restrict__ lo) {
    int idx = blockIdx.x*blockDim.x + threadIdx.x;
    if (idx >= NPAD*DD) return;
    int row = idx >> 7;
    float x = (row < VO) ? emb[idx] : 0.f;
    split1(x, hi[idx], lo[idx]);
}

// ---------------- generic HMMA GEMM -------------------------------------------
// C[M,Nc] = A[M,K] @ W[N,K]^T with bf16 3-product split (Ahi*Bhi + Ahi*Blo + Alo*Bhi).
// Block 128x128, 256 threads (8 warps 2m x 4n, warp tile 64x32). K % 32 == 0.
// HILO: write bf16 hi/lo pair instead of fp32. TAIL: guard n < Nc on stores.
#define HM_STR 40

template<bool BIAS, bool RELU, bool HILO, bool TAIL>
__global__ void __launch_bounds__(256, 1)
hmma_gemm(const bf16* __restrict__ aHi, const bf16* __restrict__ aLo,
          const bf16* __restrict__ wHi, const bf16* __restrict__ wLo,
          const float* __restrict__ bias, float* __restrict__ outF,
          bf16* __restrict__ outHi, bf16* __restrict__ outLo,
          int Nc, int K) {
    __shared__ __align__(16) bf16 sAh[128*HM_STR];
    __shared__ __align__(16) bf16 sAl[128*HM_STR];
    __shared__ __align__(16) bf16 sBh[128*HM_STR];
    __shared__ __align__(16) bf16 sBl[128*HM_STR];

    const int tid = threadIdx.x;
    const int wid = tid >> 5, lane = tid & 31;
    const int m0 = blockIdx.y * 128;
    const int n0 = blockIdx.x * 128;
    const int wm = (wid >> 2) * 64;
    const int wn = (wid & 3) * 32;

    float acc[4][4][4];
    #pragma unroll
    for (int mi = 0; mi < 4; mi++)
        #pragma unroll
        for (int ni = 0; ni < 4; ni++)
            #pragma unroll
            for (int q = 0; q < 4; q++) acc[mi][ni][q] = 0.f;

    const uint32_t uAh = smem_u32(sAh), uAl = smem_u32(sAl);
    const uint32_t uBh = smem_u32(sBh), uBl = smem_u32(sBl);

    const int nkc = K >> 5;
    for (int kc = 0; kc < nkc; kc++) {
        const int kg = kc * 32;
        #pragma unroll
        for (int t = 0; t < 2; t++) {
            int li = tid + t*256;
            int row = li >> 2;
            int co  = (li & 3) * 8;
            uint4 vah = *reinterpret_cast<const uint4*>(aHi + (size_t)(m0+row)*K + kg + co);
            uint4 val = *reinterpret_cast<const uint4*>(aLo + (size_t)(m0+row)*K + kg + co);
            uint4 vbh = *reinterpret_cast<const uint4*>(wHi + (size_t)(n0+row)*K + kg + co);
            uint4 vbl = *reinterpret_cast<const uint4*>(wLo + (size_t)(n0+row)*K + kg + co);
            *reinterpret_cast<uint4*>(&sAh[row*HM_STR + co]) = vah;
            *reinterpret_cast<uint4*>(&sAl[row*HM_STR + co]) = val;
            *reinterpret_cast<uint4*>(&sBh[row*HM_STR + co]) = vbh;
            *reinterpret_cast<uint4*>(&sBl[row*HM_STR + co]) = vbl;
        }
        __syncthreads();

        #pragma unroll
        for (int kk = 0; kk < 32; kk += 16) {
            uint32_t ah[4][4], al[4][4], bh[4][2], bl[4][2];
            #pragma unroll
            for (int mi = 0; mi < 4; mi++) {
                int r = wm + mi*16 + (lane & 15);
                int c = kk + (lane >> 4) * 8;
                uint32_t off = (uint32_t)(r*HM_STR + c) * 2;
                ldsm4(ah[mi], uAh + off);
                ldsm4(al[mi], uAl + off);
            }
            #pragma unroll
            for (int ni = 0; ni < 4; ni++) {
                int r = wn + ni*8 + (lane & 7);
                int c = kk + ((lane >> 3) & 1) * 8;
                uint32_t off = (uint32_t)(r*HM_STR + c) * 2;
                ldsm2(bh[ni], uBh + off);
                ldsm2(bl[ni], uBl + off);
            }
            #pragma unroll
            for (int mi = 0; mi < 4; mi++)
                #pragma unroll
                for (int ni = 0; ni < 4; ni++) {
                    mma16816(acc[mi][ni], ah[mi], bh[ni]);
                    mma16816(acc[mi][ni], ah[mi], bl[ni]);
                    mma16816(acc[mi][ni], al[mi], bh[ni]);
                }
        }
        __syncthreads();
    }

    #pragma unroll
    for (int mi = 0; mi < 4; mi++) {
        #pragma unroll
        for (int ni = 0; ni < 4; ni++) {
            int r = m0 + wm + mi*16 + (lane >> 2);
            int c = n0 + wn + ni*8 + (lane & 3)*2;
            float q0 = acc[mi][ni][0], q1 = acc[mi][ni][1];
            float q2 = acc[mi][ni][2], q3 = acc[mi][ni][3];
            if (BIAS) {
                float b0 = bias[c], b1 = bias[c+1];
                q0 += b0; q1 += b1; q2 += b0; q3 += b1;
            }
            if (RELU) {
                q0 = fmaxf(q0, 0.f); q1 = fmaxf(q1, 0.f);
                q2 = fmaxf(q2, 0.f); q3 = fmaxf(q3, 0.f);
            }
            if (HILO) {
                __nv_bfloat162 h0, l0, h1, l1;
                split1(q0, h0.x, l0.x); split1(q1, h0.y, l0.y);
                split1(q2, h1.x, l1.x); split1(q3, h1.y, l1.y);
                *reinterpret_cast<__nv_bfloat162*>(outHi + (size_t)r*Nc + c) = h0;
                *reinterpret_cast<__nv_bfloat162*>(outLo + (size_t)r*Nc + c) = l0;
                *reinterpret_cast<__nv_bfloat162*>(outHi + (size_t)(r+8)*Nc + c) = h1;
                *reinterpret_cast<__nv_bfloat162*>(outLo + (size_t)(r+8)*Nc + c) = l1;
            } else if (TAIL) {
                float* p0 = outF + (size_t)r*Nc + c;
                float* p1 = outF + (size_t)(r+8)*Nc + c;
                if (c < Nc)     { p0[0] = q0; p1[0] = q2; }
                if (c + 1 < Nc) { p0[1] = q1; p1[1] = q3; }
            } else {
                *reinterpret_cast<float2*>(outF + (size_t)r*Nc + c) = make_float2(q0, q1);
                *reinterpret_cast<float2*>(outF + (size_t)(r+8)*Nc + c) = make_float2(q2, q3);
            }
        }
    }
}

// ---------------- GNN rep per batch: parallel unique + CSR path edges -------
__global__ void gnn_kernel(const int* __restrict__ seq, const float* __restrict__ emb,
                           float* __restrict__ shortu) {
    int b = blockIdx.x;
    int tid = threadIdx.x;              // 128
    __shared__ int s_val[LL];
    __shared__ int s_valid[LL];
    __shared__ int s_rep[LL];
    __shared__ int s_cpos[LL];
    __shared__ int s_byc[LL];
    __shared__ int s_uniq[LL];
    __shared__ unsigned char s_A[LL][LL];
    __shared__ int s_nu, s_nv;
    __shared__ int s_rowstart[LL+1];
    __shared__ int s_colidx[LL];
    __shared__ float s_deg[LL];
    __shared__ float s_e[LL][DD];

    if (tid < LL) {
        int v = seq[b*LL + tid];
        s_val[tid] = v;
        s_valid[tid] = (v > 0);
    }
    for (int i = tid; i < LL*LL; i += 128) ((unsigned char*)s_A)[i] = 0;
    __syncthreads();

    if (tid < LL) {
        int v = s_val[tid];
        int valid = s_valid[tid];
        int rep = valid;
        int cpos = 0;
        for (int k = 0; k < tid; k++) {
            if (s_valid[k]) {
                cpos++;
                if (s_val[k] == v) rep = 0;
            }
        }
        s_rep[tid] = rep;
        s_cpos[tid] = cpos;
    }
    __syncthreads();
    if (tid < LL && s_valid[tid]) {
        int v = s_val[tid];
        int uid = 0;
        for (int j = 0; j < LL; j++)
            if (s_rep[j] && s_val[j] < v) uid++;
        s_byc[s_cpos[tid]] = uid;
        if (s_rep[tid]) s_uniq[uid] = v;
    }
    if (tid == 0) {
        int nu = 0, nv = 0;
        for (int j = 0; j < LL; j++) { nu += s_rep[j]; nv += s_valid[j]; }
        s_nu = nu; s_nv = nv;
    }
    __syncthreads();
    int nu = s_nu, nv = s_nv;

    if (nu > 1 && tid < nv - 1)
        s_A[s_byc[tid]][s_byc[tid+1]] = 1;
    __syncthreads();

    if (tid < LL) {
        int dg = 0;
        for (int j = 0; j < nu; j++) dg += s_A[tid][j];
        s_deg[tid] = (float)dg;
    }
    __syncthreads();
    if (tid == 0) {
        int acc = 0;
        for (int i = 0; i < nu; i++) { s_rowstart[i] = acc; acc += (int)s_deg[i]; }
        s_rowstart[nu] = acc;
    }
    __syncthreads();
    if (tid < nu) {
        int w = s_rowstart[tid];
        for (int j = 0; j < nu; j++)
            if (s_A[tid][j]) s_colidx[w++] = j;
    }
    for (int idx = tid; idx < nu*DD; idx += 128) {
        int i = idx >> 7, d = idx & 127;
        s_e[i][d] = emb[(size_t)s_uniq[i]*DD + d];
    }
    __syncthreads();

    int d = tid;
    float accT = 0.f;
    for (int i = 0; i < nu; i++) {
        float s = 0.f;
        int r0 = s_rowstart[i], r1 = s_rowstart[i+1];
        for (int k = r0; k < r1; k++) s += s_e[s_colidx[k]][d];
        float val = s / (s_deg[i] + 1e-8f);
        float lr = (val > 0.f) ? val : 0.01f*val;
        accT += lr + s_e[i][d];
    }
    shortu[(size_t)b*DD + d] = accT / fmaxf((float)nu, 1.0f);
}

// ---------------- GRU: all 50 steps in one kernel ----------------
#define GRU_ROWS 16
#define GRU_PAIRS 8
#define GRU_SMEM (3*DD*DD*4 + DD*GRU_PAIRS*8)

__device__ __forceinline__ float sigmf(float x) { return 1.f / (1.f + __expf(-x)); }
__device__ __forceinline__ float tanhfast(float x) {
    float e = __expf(-2.f * x);
    return (1.f - e) / (1.f + e);
}

__global__ void gru_all_kernel(const float* __restrict__ gi, const float* __restrict__ WT,
                               const float* __restrict__ bhh, const float* __restrict__ pos,
                               float* __restrict__ hseq, float* __restrict__ hpos,
                               bf16* __restrict__ hpHi, bf16* __restrict__ hpLo) {
    extern __shared__ float sm[];
    float* sW = sm;
    float2* shp = (float2*)(sm + 3*DD*DD);
    const int d = threadIdx.x;
    const int b0 = blockIdx.x * GRU_ROWS;

    for (int i = d; i < (3*DD*DD)/4; i += DD)
        reinterpret_cast<float4*>(sW)[i] = reinterpret_cast<const float4*>(WT)[i];
    #pragma unroll
    for (int p = 0; p < GRU_PAIRS; p++) shp[d*GRU_PAIRS + p] = make_float2(0.f, 0.f);
    __syncthreads();

    const float bR = bhh[d], bZ = bhh[DD+d], bN = bhh[2*DD+d];

    for (int t = 0; t < LL; t++) {
        ULL aR[GRU_PAIRS], aZ[GRU_PAIRS], aN[GRU_PAIRS];
        #pragma unroll
        for (int p = 0; p < GRU_PAIRS; p++) { aR[p]=0ull; aZ[p]=0ull; aN[p]=0ull; }

        #pragma unroll 4
        for (int k = 0; k < DD; k++) {
            float w0 = sW[k*384 + d];
            float w1 = sW[k*384 + 128 + d];
            float w2 = sW[k*384 + 256 + d];
            ULL d0 = pk2(w0, w0), d1 = pk2(w1, w1), d2 = pk2(w2, w2);
            #pragma unroll
            for (int p = 0; p < GRU_PAIRS; p++) {
                ULL hk = *reinterpret_cast<const ULL*>(&shp[k*GRU_PAIRS + p]);
                fma2(aR[p], hk, d0);
                fma2(aZ[p], hk, d1);
                fma2(aN[p], hk, d2);
            }
        }

        float posv = pos[t*DD + d];
        float hnew[GRU_ROWS];
        #pragma unroll
        for (int p = 0; p < GRU_PAIRS; p++) {
            float2 fR = upk2(aR[p]), fZ = upk2(aZ[p]), fN = upk2(aN[p]);
            float2 hold2 = shp[d*GRU_PAIRS + p];
            #pragma unroll
            for (int l = 0; l < 2; l++) {
                int r = 2*p + l;
                int b = b0 + r;
                size_t gb = ((size_t)b*LL + t)*384;
                float hr = l ? fR.y : fR.x;
                float hz = l ? fZ.y : fZ.x;
                float hn = l ? fN.y : fN.x;
                float rr = sigmf(gi[gb + d] + hr + bR);
                float zz = sigmf(gi[gb + 128 + d] + hz + bZ);
                float nn = tanhfast(gi[gb + 256 + d] + rr*(hn + bN));
                float hold = l ? hold2.y : hold2.x;
                float hv = (1.f - zz)*nn + zz*hold;
                hnew[r] = hv;
                size_t o = ((size_t)b*LL + t)*DD + d;
                float hp = hv + posv;
                hseq[o] = hv;
                hpos[o] = hp;
                split1(hp, hpHi[o], hpLo[o]);
            }
        }
        __syncthreads();
        #pragma unroll
        for (int p = 0; p < GRU_PAIRS; p++)
            shp[d*GRU_PAIRS + p] = make_float2(hnew[2*p], hnew[2*p+1]);
        __syncthreads();
    }
}

// ---------------- attention (one block per (b,h)); emits bf16 hi/lo ----------
__global__ void attn_kernel(const float* __restrict__ qkv,
                            bf16* __restrict__ aoHi, bf16* __restrict__ aoLo) {
    int b = blockIdx.x, h = blockIdx.y;
    __shared__ float sq[LL][64];
    __shared__ float sk[LL][65];
    __shared__ float sv[LL][64];
    __shared__ float S[LL][LL];
    int tid = threadIdx.x;
    const float* base = qkv + ((size_t)b*LL)*384 + h*64;
    for (int idx = tid; idx < LL*64; idx += 128) {
        int l = idx >> 6, dd = idx & 63;
        sq[l][dd] = base[l*384 + dd];
        sk[l][dd] = base[l*384 + 128 + dd];
        sv[l][dd] = base[l*384 + 256 + dd];
    }
    __syncthreads();
    for (int idx = tid; idx < LL*LL; idx += 128) {
        int i = idx / LL, j = idx % LL;
        float s = 0.f;
        #pragma unroll
        for (int dd = 0; dd < 64; dd++) s = fmaf(sq[i][dd], sk[j][dd], s);
        S[i][j] = s * 0.125f;
    }
    __syncthreads();
    if (tid < LL) {
        float mx = -1e30f;
        for (int j = 0; j < LL; j++) mx = fmaxf(mx, S[tid][j]);
        float sum = 0.f;
        for (int j = 0; j < LL; j++) { float e = __expf(S[tid][j]-mx); S[tid][j] = e; sum += e; }
        float inv = 1.f/sum;
        for (int j = 0; j < LL; j++) S[tid][j] *= inv;
    }
    __syncthreads();
    size_t obase = ((size_t)b*LL)*DD + h*64;
    for (int idx = tid; idx < LL*64; idx += 128) {
        int i = idx >> 6, dd = idx & 63;
        float s = 0.f;
        for (int j = 0; j < LL; j++) s = fmaf(S[i][j], sv[j][dd], s);
        size_t o = obase + (size_t)i*DD + dd;
        split1(s, aoHi[o], aoLo[o]);
    }
}

// ---------------- layernorm on (x+y), warp per row (optional hi/lo out) ------
template<bool HILO>
__global__ void ln_kernel(const float* __restrict__ x, const float* __restrict__ y,
                          const float* __restrict__ g, const float* __restrict__ bta,
                          float* __restrict__ out, bf16* __restrict__ oHi,
                          bf16* __restrict__ oLo, int rows) {
    int row = blockIdx.x * 8 + (threadIdx.x >> 5);
    int lane = threadIdx.x & 31;
    if (row >= rows) return;
    const float* px = x + (size_t)row*DD;
    const float* py = y + (size_t)row*DD;
    float v[4]; float s = 0.f;
    #pragma unroll
    for (int i=0;i<4;i++){ v[i] = px[lane+32*i] + py[lane+32*i]; s += v[i]; }
    #pragma unroll
    for (int o=16;o>0;o>>=1) s += __shfl_xor_sync(0xffffffffu, s, o);
    float m = s * (1.f/128.f);
    float vs = 0.f;
    #pragma unroll
    for (int i=0;i<4;i++){ float dv = v[i]-m; vs += dv*dv; }
    #pragma unroll
    for (int o=16;o>0;o>>=1) vs += __shfl_xor_sync(0xffffffffu, vs, o);
    float inv = rsqrtf(vs*(1.f/128.f) + 1e-5f);
    #pragma unroll
    for (int i=0;i<4;i++){
        int c = lane+32*i;
        float val = (v[i]-m)*inv*g[c] + bta[c];
        size_t o = (size_t)row*DD + c;
        out[o] = val;
        if (HILO) split1(val, oHi[o], oLo[o]);
    }
}

// ---------------- pooling + e_hat (emits bf16 hi/lo split) ----------------
__global__ void pool_kernel(const int* __restrict__ seq, const float* __restrict__ hseq,
                            const float* __restrict__ hattn, const float* __restrict__ shortu,
                            bf16* __restrict__ aHi, bf16* __restrict__ aLo) {
    int b = blockIdx.x;
    int d = threadIdx.x;
    float a1 = 0.f, a2 = 0.f; int cnt = 0;
    for (int l = 0; l < LL; l++) {
        if (seq[b*LL + l] > 0) {
            cnt++;
            a1 += hseq[((size_t)b*LL + l)*DD + d];
            a2 += hattn[((size_t)b*LL + l)*DD + d];
        }
    }
    float len = fmaxf((float)cnt, 1.0f);
    float val = shortu[(size_t)b*DD + d] + (a1 + a2) / len;
    split1(val, aHi[(size_t)b*DD + d], aLo[(size_t)b*DD + d]);
}

// ---------------- host launcher ----------------
static float* symf(const void* sym) { void* p = nullptr; cudaGetSymbolAddress(&p, sym); return (float*)p; }
static bf16* symb(const void* sym) { void* p = nullptr; cudaGetSymbolAddress(&p, sym); return (bf16*)p; }

extern "C" void kernel_launch(void* const* d_in, const int* in_sizes, int n_in,
                              void* d_out, int out_size) {
    const int*   seq       = (const int*)  d_in[0];
    const float* item_emb  = (const float*)d_in[1];
    const float* pos_emb   = (const float*)d_in[2];
    const float* gru_wih   = (const float*)d_in[3];
    const float* gru_whh   = (const float*)d_in[4];
    const float* gru_bih   = (const float*)d_in[5];
    const float* gru_bhh   = (const float*)d_in[6];
    const float* in_proj_w = (const float*)d_in[7];
    const float* in_proj_b = (const float*)d_in[8];
    const float* out_proj_w= (const float*)d_in[9];
    const float* out_proj_b= (const float*)d_in[10];
    const float* ln1_g     = (const float*)d_in[11];
    const float* ln1_b     = (const float*)d_in[12];
    const float* ln2_g     = (const float*)d_in[13];
    const float* ln2_b     = (const float*)d_in[14];
    const float* ff1_w     = (const float*)d_in[15];
    const float* ff1_b     = (const float*)d_in[16];
    const float* ff2_w     = (const float*)d_in[17];
    const float* ff2_b     = (const float*)d_in[18];
    float* out = (float*)d_out;

    bf16* pxHi  = symb(g_xHi);   bf16* pxLo  = symb(g_xLo);
    float* pgi   = symf(g_gi);
    float* phseq = symf(g_hseq);
    float* phpos = symf(g_hpos);
    bf16* phpHi = symb(g_hposHi); bf16* phpLo = symb(g_hposLo);
    float* pqkv  = symf(g_qkv);
    bf16* paoHi = symb(g_attnoHi); bf16* paoLo = symb(g_attnoLo);
    float* poproj= symf(g_oproj);
    float* ph1   = symf(g_h1);
    bf16* ph1Hi = symb(g_h1Hi);  bf16* ph1Lo = symb(g_h1Lo);
    bf16* pffHi = symb(g_ffHi);  bf16* pffLo = symb(g_ffLo);
    float* pff2  = symf(g_ff2);
    float* phattn= symf(g_hattn);
    float* pshort= symf(g_short);
    float* pWT   = symf(g_WT);
    bf16* pwHi  = symb(g_wHi);   bf16* pwLo  = symb(g_wLo);
    bf16* paHi  = symb(g_aHi);   bf16* paLo  = symb(g_aLo);
    bf16* pwihHi= symb(g_wihHi); bf16* pwihLo= symb(g_wihLo);
    bf16* pinpHi= symb(g_inpHi); bf16* pinpLo= symb(g_inpLo);
    bf16* popHi = symb(g_opHi);  bf16* popLo = symb(g_opLo);
    bf16* pf1Hi = symb(g_f1Hi);  bf16* pf1Lo = symb(g_f1Lo);
    bf16* pf2Hi = symb(g_f2Hi);  bf16* pf2Lo = symb(g_f2Lo);

    cudaFuncSetAttribute(gru_all_kernel, cudaFuncAttributeMaxDynamicSharedMemorySize, GRU_SMEM);

    const int totBLD = BLr*DD;

    // weight preprocessing
    transpose_whh<<<(3*DD*DD+255)/256, 256>>>(gru_whh, pWT);
    split_w_kernel<<<(384*DD+255)/256, 256>>>(gru_wih, pwihHi, pwihLo, 384*DD);
    split_w_kernel<<<(384*DD+255)/256, 256>>>(in_proj_w, pinpHi, pinpLo, 384*DD);
    split_w_kernel<<<(DD*DD+255)/256, 256>>>(out_proj_w, popHi, popLo, DD*DD);
    split_w_kernel<<<(512*DD+255)/256, 256>>>(ff1_w, pf1Hi, pf1Lo, 512*DD);
    split_w_kernel<<<(DD*512+255)/256, 256>>>(ff2_w, pf2Hi, pf2Lo, DD*512);
    split_emb_kernel<<<(NPAD*DD+255)/256, 256>>>(item_emb, pwHi, pwLo);

    // embedding gather (bf16 hi/lo)
    embed_hilo_kernel<<<(totBLD+255)/256, 256>>>(seq, item_emb, pxHi, pxLo);

    // gi = x @ Wih^T + bih    (M=BLr, N=384, K=128)
    {
        dim3 grid(384/128, BLr/128);
        hmma_gemm<true,false,false,false><<<grid, 256>>>(pxHi, pxLo, pwihHi, pwihLo,
            gru_bih, pgi, nullptr, nullptr, 384, DD);
    }
    // GRU (writes hseq, hpos fp32 + hpos hi/lo)
    gru_all_kernel<<<BB/GRU_ROWS, DD, GRU_SMEM>>>(pgi, pWT, gru_bhh, pos_emb,
        phseq, phpos, phpHi, phpLo);
    // qkv = hpos @ in_proj^T + b   (N=384, K=128)
    {
        dim3 grid(384/128, BLr/128);
        hmma_gemm<true,false,false,false><<<grid, 256>>>(phpHi, phpLo, pinpHi, pinpLo,
            in_proj_b, pqkv, nullptr, nullptr, 384, DD);
    }
    // attention -> attno hi/lo
    {
        dim3 grid(BB, 2);
        attn_kernel<<<grid, 128>>>(pqkv, paoHi, paoLo);
    }
    // GNN short_u
    gnn_kernel<<<BB, 128>>>(seq, item_emb, pshort);
    // out_proj  (N=128, K=128)
    {
        dim3 grid(1, BLr/128);
        hmma_gemm<true,false,false,false><<<grid, 256>>>(paoHi, paoLo, popHi, popLo,
            out_proj_b, poproj, nullptr, nullptr, DD, DD);
    }
    // ln1 (fp32 + hi/lo)
    ln_kernel<true><<<BLr/8, 256>>>(phpos, poproj, ln1_g, ln1_b, ph1, ph1Hi, ph1Lo, BLr);
    // ff1 (relu, bf16 hi/lo out)  (N=512, K=128)
    {
        dim3 grid(512/128, BLr/128);
        hmma_gemm<true,true,true,false><<<grid, 256>>>(ph1Hi, ph1Lo, pf1Hi, pf1Lo,
            ff1_b, nullptr, pffHi, pffLo, 512, DD);
    }
    // ff2  (N=128, K=512)
    {
        dim3 grid(1, BLr/128);
        hmma_gemm<true,false,false,false><<<grid, 256>>>(pffHi, pffLo, pf2Hi, pf2Lo,
            ff2_b, pff2, nullptr, nullptr, DD, 512);
    }
    // ln2 (fp32 only)
    ln_kernel<false><<<BLr/8, 256>>>(ph1, pff2, ln2_g, ln2_b, phattn, nullptr, nullptr, BLr);
    // pooling -> e_hat hi/lo
    pool_kernel<<<BB, 128>>>(seq, phseq, phattn, pshort, paHi, paLo);
    // logits  (M=2048, N=NPAD tiles, Nc=VO, K=128)
    {
        dim3 grid(NPAD/128, BB/128);
        hmma_gemm<false,false,false,true><<<grid, 256>>>(paHi, paLo, pwHi, pwLo,
            nullptr, out, nullptr, nullptr, VO, DD);
    }
}

// round 17
// speedup vs baseline: 1.0146x; 1.0146x over previous
#include <cuda_runtime.h>
#include <cuda_bf16.h>
#include <cstdint>
#include <stdint.h>
#include <math.h>

#define BB 2048
#define LL 50
#define DD 128
#define VO 50001
#define NPAD 50048           // 391 * 128
#define BLr (BB*LL)          // 102400 rows

typedef unsigned long long ULL;
typedef __nv_bfloat16 bf16;

// ---------------- f32x2 helpers ----------------
__device__ __forceinline__ ULL pk2(float lo, float hi) {
    ULL r; asm("mov.b64 %0,{%1,%2};" : "=l"(r) : "f"(lo), "f"(hi)); return r;
}
__device__ __forceinline__ void fma2(ULL& d, ULL a, ULL b) {
    asm("fma.rn.f32x2 %0,%1,%2,%0;" : "+l"(d) : "l"(a), "l"(b));
}
__device__ __forceinline__ float2 upk2(ULL v) {
    float2 r; asm("mov.b64 {%0,%1},%2;" : "=f"(r.x), "=f"(r.y) : "l"(v)); return r;
}

// ---------------- mma.sync helpers ----------------
__device__ __forceinline__ uint32_t smem_u32(const void* p) {
    uint32_t a; asm("{ .reg .u64 t; cvta.to.shared.u64 t, %1; cvt.u32.u64 %0, t; }" : "=r"(a) : "l"(p));
    return a;
}
__device__ __forceinline__ void ldsm4(uint32_t* r, uint32_t addr) {
    asm volatile("ldmatrix.sync.aligned.m8n8.x4.shared.b16 {%0,%1,%2,%3}, [%4];"
        : "=r"(r[0]), "=r"(r[1]), "=r"(r[2]), "=r"(r[3]) : "r"(addr));
}
__device__ __forceinline__ void ldsm2(uint32_t* r, uint32_t addr) {
    asm volatile("ldmatrix.sync.aligned.m8n8.x2.shared.b16 {%0,%1}, [%2];"
        : "=r"(r[0]), "=r"(r[1]) : "r"(addr));
}
__device__ __forceinline__ void mma16816(float* c, const uint32_t* a, const uint32_t* b) {
    asm volatile("mma.sync.aligned.m16n8k16.row.col.f32.bf16.bf16.f32 "
        "{%0,%1,%2,%3}, {%4,%5,%6,%7}, {%8,%9}, {%0,%1,%2,%3};"
        : "+f"(c[0]), "+f"(c[1]), "+f"(c[2]), "+f"(c[3])
        : "r"(a[0]), "r"(a[1]), "r"(a[2]), "r"(a[3]), "r"(b[0]), "r"(b[1]));
}
__device__ __forceinline__ void split1(float v, bf16& h, bf16& l) {
    h = __float2bfloat16(v);
    l = __float2bfloat16(v - __bfloat162float(h));
}

// ---------------- scratch ----------------
__device__ bf16  g_xHi[(size_t)BLr*DD];
__device__ bf16  g_xLo[(size_t)BLr*DD];
__device__ float g_gi[(size_t)BLr*3*DD];
__device__ float g_hseq[(size_t)BLr*DD];
__device__ float g_hpos[(size_t)BLr*DD];
__device__ bf16  g_hposHi[(size_t)BLr*DD];
__device__ bf16  g_hposLo[(size_t)BLr*DD];
__device__ float g_qkv[(size_t)BLr*3*DD];
__device__ bf16  g_attnoHi[(size_t)BLr*DD];
__device__ bf16  g_attnoLo[(size_t)BLr*DD];
__device__ float g_oproj[(size_t)BLr*DD];
__device__ float g_h1[(size_t)BLr*DD];
__device__ bf16  g_h1Hi[(size_t)BLr*DD];
__device__ bf16  g_h1Lo[(size_t)BLr*DD];
__device__ bf16  g_ffHi[(size_t)BLr*4*DD];
__device__ bf16  g_ffLo[(size_t)BLr*4*DD];
__device__ float g_ff2[(size_t)BLr*DD];
__device__ float g_hattn[(size_t)BLr*DD];
__device__ float g_short[(size_t)BB*DD];
__device__ float g_WT[(size_t)DD*3*DD];
__device__ bf16  g_wHi[(size_t)NPAD*DD];
__device__ bf16  g_wLo[(size_t)NPAD*DD];
__device__ bf16  g_aHi[(size_t)BB*DD];
__device__ bf16  g_aLo[(size_t)BB*DD];
// weight splits
__device__ bf16  g_wihHi[384*DD],  g_wihLo[384*DD];
__device__ bf16  g_inpHi[384*DD],  g_inpLo[384*DD];
__device__ bf16  g_opHi[DD*DD],    g_opLo[DD*DD];
__device__ bf16  g_f1Hi[512*DD],   g_f1Lo[512*DD];
__device__ bf16  g_f2Hi[DD*512],   g_f2Lo[DD*512];

// ---------------- small elementwise kernels ----------------
__global__ void embed_hilo_kernel(const int* __restrict__ seq, const float* __restrict__ emb,
                                  bf16* __restrict__ xh, bf16* __restrict__ xl) {
    int idx = blockIdx.x*blockDim.x + threadIdx.x;
    if (idx >= BLr*DD) return;
    int bl = idx >> 7; int d = idx & 127;
    int s = seq[bl];
    float v = (s > 0) ? emb[(size_t)s*DD + d] : 0.f;
    split1(v, xh[idx], xl[idx]);
}

__global__ void transpose_whh(const float* __restrict__ whh, float* __restrict__ WT) {
    int idx = blockIdx.x*blockDim.x + threadIdx.x;
    if (idx >= 3*DD*DD) return;
    int c = idx / DD, k = idx % DD;
    WT[k*(3*DD) + c] = whh[idx];
}

__global__ void split_w_kernel(const float* __restrict__ src, bf16* __restrict__ hi,
                               bf16* __restrict__ lo, int n) {
    int idx = blockIdx.x*blockDim.x + threadIdx.x;
    if (idx >= n) return;
    split1(src[idx], hi[idx], lo[idx]);
}

__global__ void split_emb_kernel(const float* __restrict__ emb,
                                 bf16* __restrict__ hi, bf16* __restrict__ lo) {
    int idx = blockIdx.x*blockDim.x + threadIdx.x;
    if (idx >= NPAD*DD) return;
    int row = idx >> 7;
    float x = (row < VO) ? emb[idx] : 0.f;
    split1(x, hi[idx], lo[idx]);
}

// ---------------- generic HMMA GEMM -------------------------------------------
// C[M,Nc] = A[M,K] @ W[N,K]^T with bf16 3-product split (Ahi*Bhi + Ahi*Blo + Alo*Bhi).
// Block 128x128, 256 threads (8 warps 2m x 4n, warp tile 64x32). K % 32 == 0.
// HILO: write bf16 hi/lo pair instead of fp32. TAIL: guard n < Nc on stores.
#define HM_STR 40

template<bool BIAS, bool RELU, bool HILO, bool TAIL>
__global__ void __launch_bounds__(256, 1)
hmma_gemm(const bf16* __restrict__ aHi, const bf16* __restrict__ aLo,
          const bf16* __restrict__ wHi, const bf16* __restrict__ wLo,
          const float* __restrict__ bias, float* __restrict__ outF,
          bf16* __restrict__ outHi, bf16* __restrict__ outLo,
          int Nc, int K) {
    __shared__ __align__(16) bf16 sAh[128*HM_STR];
    __shared__ __align__(16) bf16 sAl[128*HM_STR];
    __shared__ __align__(16) bf16 sBh[128*HM_STR];
    __shared__ __align__(16) bf16 sBl[128*HM_STR];

    const int tid = threadIdx.x;
    const int wid = tid >> 5, lane = tid & 31;
    const int m0 = blockIdx.y * 128;
    const int n0 = blockIdx.x * 128;
    const int wm = (wid >> 2) * 64;
    const int wn = (wid & 3) * 32;

    float acc[4][4][4];
    #pragma unroll
    for (int mi = 0; mi < 4; mi++)
        #pragma unroll
        for (int ni = 0; ni < 4; ni++)
            #pragma unroll
            for (int q = 0; q < 4; q++) acc[mi][ni][q] = 0.f;

    const uint32_t uAh = smem_u32(sAh), uAl = smem_u32(sAl);
    const uint32_t uBh = smem_u32(sBh), uBl = smem_u32(sBl);

    const int nkc = K >> 5;
    for (int kc = 0; kc < nkc; kc++) {
        const int kg = kc * 32;
        #pragma unroll
        for (int t = 0; t < 2; t++) {
            int li = tid + t*256;
            int row = li >> 2;
            int co  = (li & 3) * 8;
            uint4 vah = *reinterpret_cast<const uint4*>(aHi + (size_t)(m0+row)*K + kg + co);
            uint4 val = *reinterpret_cast<const uint4*>(aLo + (size_t)(m0+row)*K + kg + co);
            uint4 vbh = *reinterpret_cast<const uint4*>(wHi + (size_t)(n0+row)*K + kg + co);
            uint4 vbl = *reinterpret_cast<const uint4*>(wLo + (size_t)(n0+row)*K + kg + co);
            *reinterpret_cast<uint4*>(&sAh[row*HM_STR + co]) = vah;
            *reinterpret_cast<uint4*>(&sAl[row*HM_STR + co]) = val;
            *reinterpret_cast<uint4*>(&sBh[row*HM_STR + co]) = vbh;
            *reinterpret_cast<uint4*>(&sBl[row*HM_STR + co]) = vbl;
        }
        __syncthreads();

        #pragma unroll
        for (int kk = 0; kk < 32; kk += 16) {
            uint32_t ah[4][4], al[4][4], bh[4][2], bl[4][2];
            #pragma unroll
            for (int mi = 0; mi < 4; mi++) {
                int r = wm + mi*16 + (lane & 15);
                int c = kk + (lane >> 4) * 8;
                uint32_t off = (uint32_t)(r*HM_STR + c) * 2;
                ldsm4(ah[mi], uAh + off);
                ldsm4(al[mi], uAl + off);
            }
            #pragma unroll
            for (int ni = 0; ni < 4; ni++) {
                int r = wn + ni*8 + (lane & 7);
                int c = kk + ((lane >> 3) & 1) * 8;
                uint32_t off = (uint32_t)(r*HM_STR + c) * 2;
                ldsm2(bh[ni], uBh + off);
                ldsm2(bl[ni], uBl + off);
            }
            #pragma unroll
            for (int mi = 0; mi < 4; mi++)
                #pragma unroll
                for (int ni = 0; ni < 4; ni++) {
                    mma16816(acc[mi][ni], ah[mi], bh[ni]);
                    mma16816(acc[mi][ni], ah[mi], bl[ni]);
                    mma16816(acc[mi][ni], al[mi], bh[ni]);
                }
        }
        __syncthreads();
    }

    #pragma unroll
    for (int mi = 0; mi < 4; mi++) {
        #pragma unroll
        for (int ni = 0; ni < 4; ni++) {
            int r = m0 + wm + mi*16 + (lane >> 2);
            int c = n0 + wn + ni*8 + (lane & 3)*2;
            float q0 = acc[mi][ni][0], q1 = acc[mi][ni][1];
            float q2 = acc[mi][ni][2], q3 = acc[mi][ni][3];
            if (BIAS) {
                float b0 = bias[c], b1 = bias[c+1];
                q0 += b0; q1 += b1; q2 += b0; q3 += b1;
            }
            if (RELU) {
                q0 = fmaxf(q0, 0.f); q1 = fmaxf(q1, 0.f);
                q2 = fmaxf(q2, 0.f); q3 = fmaxf(q3, 0.f);
            }
            if (HILO) {
                __nv_bfloat162 h0, l0, h1, l1;
                split1(q0, h0.x, l0.x); split1(q1, h0.y, l0.y);
                split1(q2, h1.x, l1.x); split1(q3, h1.y, l1.y);
                *reinterpret_cast<__nv_bfloat162*>(outHi + (size_t)r*Nc + c) = h0;
                *reinterpret_cast<__nv_bfloat162*>(outLo + (size_t)r*Nc + c) = l0;
                *reinterpret_cast<__nv_bfloat162*>(outHi + (size_t)(r+8)*Nc + c) = h1;
                *reinterpret_cast<__nv_bfloat162*>(outLo + (size_t)(r+8)*Nc + c) = l1;
            } else if (TAIL) {
                float* p0 = outF + (size_t)r*Nc + c;
                float* p1 = outF + (size_t)(r+8)*Nc + c;
                if (c < Nc)     { p0[0] = q0; p1[0] = q2; }
                if (c + 1 < Nc) { p0[1] = q1; p1[1] = q3; }
            } else {
                *reinterpret_cast<float2*>(outF + (size_t)r*Nc + c) = make_float2(q0, q1);
                *reinterpret_cast<float2*>(outF + (size_t)(r+8)*Nc + c) = make_float2(q2, q3);
            }
        }
    }
}

// ---------------- GNN rep per batch: parallel unique + CSR path edges -------
__global__ void gnn_kernel(const int* __restrict__ seq, const float* __restrict__ emb,
                           float* __restrict__ shortu) {
    int b = blockIdx.x;
    int tid = threadIdx.x;              // 128
    __shared__ int s_val[LL];
    __shared__ int s_valid[LL];
    __shared__ int s_rep[LL];
    __shared__ int s_cpos[LL];
    __shared__ int s_byc[LL];
    __shared__ int s_uniq[LL];
    __shared__ unsigned char s_A[LL][LL];
    __shared__ int s_nu, s_nv;
    __shared__ int s_rowstart[LL+1];
    __shared__ int s_colidx[LL];
    __shared__ float s_deg[LL];
    __shared__ float s_e[LL][DD];

    if (tid < LL) {
        int v = seq[b*LL + tid];
        s_val[tid] = v;
        s_valid[tid] = (v > 0);
    }
    for (int i = tid; i < LL*LL; i += 128) ((unsigned char*)s_A)[i] = 0;
    __syncthreads();

    if (tid < LL) {
        int v = s_val[tid];
        int valid = s_valid[tid];
        int rep = valid;
        int cpos = 0;
        for (int k = 0; k < tid; k++) {
            if (s_valid[k]) {
                cpos++;
                if (s_val[k] == v) rep = 0;
            }
        }
        s_rep[tid] = rep;
        s_cpos[tid] = cpos;
    }
    __syncthreads();
    if (tid < LL && s_valid[tid]) {
        int v = s_val[tid];
        int uid = 0;
        for (int j = 0; j < LL; j++)
            if (s_rep[j] && s_val[j] < v) uid++;
        s_byc[s_cpos[tid]] = uid;
        if (s_rep[tid]) s_uniq[uid] = v;
    }
    if (tid == 0) {
        int nu = 0, nv = 0;
        for (int j = 0; j < LL; j++) { nu += s_rep[j]; nv += s_valid[j]; }
        s_nu = nu; s_nv = nv;
    }
    __syncthreads();
    int nu = s_nu, nv = s_nv;

    if (nu > 1 && tid < nv - 1)
        s_A[s_byc[tid]][s_byc[tid+1]] = 1;
    __syncthreads();

    if (tid < LL) {
        int dg = 0;
        for (int j = 0; j < nu; j++) dg += s_A[tid][j];
        s_deg[tid] = (float)dg;
    }
    __syncthreads();
    if (tid == 0) {
        int acc = 0;
        for (int i = 0; i < nu; i++) { s_rowstart[i] = acc; acc += (int)s_deg[i]; }
        s_rowstart[nu] = acc;
    }
    __syncthreads();
    if (tid < nu) {
        int w = s_rowstart[tid];
        for (int j = 0; j < nu; j++)
            if (s_A[tid][j]) s_colidx[w++] = j;
    }
    for (int idx = tid; idx < nu*DD; idx += 128) {
        int i = idx >> 7, d = idx & 127;
        s_e[i][d] = emb[(size_t)s_uniq[i]*DD + d];
    }
    __syncthreads();

    int d = tid;
    float accT = 0.f;
    for (int i = 0; i < nu; i++) {
        float s = 0.f;
        int r0 = s_rowstart[i], r1 = s_rowstart[i+1];
        for (int k = r0; k < r1; k++) s += s_e[s_colidx[k]][d];
        float val = s / (s_deg[i] + 1e-8f);
        float lr = (val > 0.f) ? val : 0.01f*val;
        accT += lr + s_e[i][d];
    }
    shortu[(size_t)b*DD + d] = accT / fmaxf((float)nu, 1.0f);
}

// ---------------- GRU: all 50 steps in one kernel ----------------
#define GRU_ROWS 16
#define GRU_PAIRS 8
#define GRU_SMEM (3*DD*DD*4 + DD*GRU_PAIRS*8)

__device__ __forceinline__ float sigmf(float x) { return 1.f / (1.f + __expf(-x)); }
__device__ __forceinline__ float tanhfast(float x) {
    float e = __expf(-2.f * x);
    return (1.f - e) / (1.f + e);
}

__global__ void gru_all_kernel(const float* __restrict__ gi, const float* __restrict__ WT,
                               const float* __restrict__ bhh, const float* __restrict__ pos,
                               float* __restrict__ hseq, float* __restrict__ hpos,
                               bf16* __restrict__ hpHi, bf16* __restrict__ hpLo) {
    extern __shared__ float sm[];
    float* sW = sm;
    float2* shp = (float2*)(sm + 3*DD*DD);
    const int d = threadIdx.x;
    const int b0 = blockIdx.x * GRU_ROWS;

    for (int i = d; i < (3*DD*DD)/4; i += DD)
        reinterpret_cast<float4*>(sW)[i] = reinterpret_cast<const float4*>(WT)[i];
    #pragma unroll
    for (int p = 0; p < GRU_PAIRS; p++) shp[d*GRU_PAIRS + p] = make_float2(0.f, 0.f);
    __syncthreads();

    const float bR = bhh[d], bZ = bhh[DD+d], bN = bhh[2*DD+d];

    for (int t = 0; t < LL; t++) {
        ULL aR[GRU_PAIRS], aZ[GRU_PAIRS], aN[GRU_PAIRS];
        #pragma unroll
        for (int p = 0; p < GRU_PAIRS; p++) { aR[p]=0ull; aZ[p]=0ull; aN[p]=0ull; }

        #pragma unroll 4
        for (int k = 0; k < DD; k++) {
            float w0 = sW[k*384 + d];
            float w1 = sW[k*384 + 128 + d];
            float w2 = sW[k*384 + 256 + d];
            ULL d0 = pk2(w0, w0), d1 = pk2(w1, w1), d2 = pk2(w2, w2);
            #pragma unroll
            for (int p = 0; p < GRU_PAIRS; p++) {
                ULL hk = *reinterpret_cast<const ULL*>(&shp[k*GRU_PAIRS + p]);
                fma2(aR[p], hk, d0);
                fma2(aZ[p], hk, d1);
                fma2(aN[p], hk, d2);
            }
        }

        float posv = pos[t*DD + d];
        float hnew[GRU_ROWS];
        #pragma unroll
        for (int p = 0; p < GRU_PAIRS; p++) {
            float2 fR = upk2(aR[p]), fZ = upk2(aZ[p]), fN = upk2(aN[p]);
            float2 hold2 = shp[d*GRU_PAIRS + p];
            #pragma unroll
            for (int l = 0; l < 2; l++) {
                int r = 2*p + l;
                int b = b0 + r;
                size_t gb = ((size_t)b*LL + t)*384;
                float hr = l ? fR.y : fR.x;
                float hz = l ? fZ.y : fZ.x;
                float hn = l ? fN.y : fN.x;
                float rr = sigmf(gi[gb + d] + hr + bR);
                float zz = sigmf(gi[gb + 128 + d] + hz + bZ);
                float nn = tanhfast(gi[gb + 256 + d] + rr*(hn + bN));
                float hold = l ? hold2.y : hold2.x;
                float hv = (1.f - zz)*nn + zz*hold;
                hnew[r] = hv;
                size_t o = ((size_t)b*LL + t)*DD + d;
                float hp = hv + posv;
                hseq[o] = hv;
                hpos[o] = hp;
                split1(hp, hpHi[o], hpLo[o]);
            }
        }
        __syncthreads();
        #pragma unroll
        for (int p = 0; p < GRU_PAIRS; p++)
            shp[d*GRU_PAIRS + p] = make_float2(hnew[2*p], hnew[2*p+1]);
        __syncthreads();
    }
}

// ---------------- attention (one block per (b,h)); emits bf16 hi/lo ----------
__global__ void attn_kernel(const float* __restrict__ qkv,
                            bf16* __restrict__ aoHi, bf16* __restrict__ aoLo) {
    int b = blockIdx.x, h = blockIdx.y;
    __shared__ float sq[LL][64];
    __shared__ float sk[LL][65];
    __shared__ float sv[LL][64];
    __shared__ float S[LL][LL];
    int tid = threadIdx.x;
    const float* base = qkv + ((size_t)b*LL)*384 + h*64;
    for (int idx = tid; idx < LL*64; idx += 128) {
        int l = idx >> 6, dd = idx & 63;
        sq[l][dd] = base[l*384 + dd];
        sk[l][dd] = base[l*384 + 128 + dd];
        sv[l][dd] = base[l*384 + 256 + dd];
    }
    __syncthreads();
    for (int idx = tid; idx < LL*LL; idx += 128) {
        int i = idx / LL, j = idx % LL;
        float s = 0.f;
        #pragma unroll
        for (int dd = 0; dd < 64; dd++) s = fmaf(sq[i][dd], sk[j][dd], s);
        S[i][j] = s * 0.125f;
    }
    __syncthreads();
    if (tid < LL) {
        float mx = -1e30f;
        for (int j = 0; j < LL; j++) mx = fmaxf(mx, S[tid][j]);
        float sum = 0.f;
        for (int j = 0; j < LL; j++) { float e = __expf(S[tid][j]-mx); S[tid][j] = e; sum += e; }
        float inv = 1.f/sum;
        for (int j = 0; j < LL; j++) S[tid][j] *= inv;
    }
    __syncthreads();
    size_t obase = ((size_t)b*LL)*DD + h*64;
    for (int idx = tid; idx < LL*64; idx += 128) {
        int i = idx >> 6, dd = idx & 63;
        float s = 0.f;
        for (int j = 0; j < LL; j++) s = fmaf(S[i][j], sv[j][dd], s);
        size_t o = obase + (size_t)i*DD + dd;
        split1(s, aoHi[o], aoLo[o]);
    }
}

// ---------------- layernorm on (x+y), warp per row (optional hi/lo out) ------
template<bool HILO>
__global__ void ln_kernel(const float* __restrict__ x, const float* __restrict__ y,
                          const float* __restrict__ g, const float* __restrict__ bta,
                          float* __restrict__ out, bf16* __restrict__ oHi,
                          bf16* __restrict__ oLo, int rows) {
    int row = blockIdx.x * 8 + (threadIdx.x >> 5);
    int lane = threadIdx.x & 31;
    if (row >= rows) return;
    const float* px = x + (size_t)row*DD;
    const float* py = y + (size_t)row*DD;
    float v[4]; float s = 0.f;
    #pragma unroll
    for (int i=0;i<4;i++){ v[i] = px[lane+32*i] + py[lane+32*i]; s += v[i]; }
    #pragma unroll
    for (int o=16;o>0;o>>=1) s += __shfl_xor_sync(0xffffffffu, s, o);
    float m = s * (1.f/128.f);
    float vs = 0.f;
    #pragma unroll
    for (int i=0;i<4;i++){ float dv = v[i]-m; vs += dv*dv; }
    #pragma unroll
    for (int o=16;o>0;o>>=1) vs += __shfl_xor_sync(0xffffffffu, vs, o);
    float inv = rsqrtf(vs*(1.f/128.f) + 1e-5f);
    #pragma unroll
    for (int i=0;i<4;i++){
        int c = lane+32*i;
        float val = (v[i]-m)*inv*g[c] + bta[c];
        size_t o = (size_t)row*DD + c;
        out[o] = val;
        if (HILO) split1(val, oHi[o], oLo[o]);
    }
}

// ---------------- pooling + e_hat (emits bf16 hi/lo split) ----------------
__global__ void pool_kernel(const int* __restrict__ seq, const float* __restrict__ hseq,
                            const float* __restrict__ hattn, const float* __restrict__ shortu,
                            bf16* __restrict__ aHi, bf16* __restrict__ aLo) {
    int b = blockIdx.x;
    int d = threadIdx.x;
    float a1 = 0.f, a2 = 0.f; int cnt = 0;
    for (int l = 0; l < LL; l++) {
        if (seq[b*LL + l] > 0) {
            cnt++;
            a1 += hseq[((size_t)b*LL + l)*DD + d];
            a2 += hattn[((size_t)b*LL + l)*DD + d];
        }
    }
    float len = fmaxf((float)cnt, 1.0f);
    float val = shortu[(size_t)b*DD + d] + (a1 + a2) / len;
    split1(val, aHi[(size_t)b*DD + d], aLo[(size_t)b*DD + d]);
}

// ---------------- host launcher ----------------
static float* symf(const void* sym) { void* p = nullptr; cudaGetSymbolAddress(&p, sym); return (float*)p; }
static bf16* symb(const void* sym) { void* p = nullptr; cudaGetSymbolAddress(&p, sym); return (bf16*)p; }

extern "C" void kernel_launch(void* const* d_in, const int* in_sizes, int n_in,
                              void* d_out, int out_size) {
    const int*   seq       = (const int*)  d_in[0];
    const float* item_emb  = (const float*)d_in[1];
    const float* pos_emb   = (const float*)d_in[2];
    const float* gru_wih   = (const float*)d_in[3];
    const float* gru_whh   = (const float*)d_in[4];
    const float* gru_bih   = (const float*)d_in[5];
    const float* gru_bhh   = (const float*)d_in[6];
    const float* in_proj_w = (const float*)d_in[7];
    const float* in_proj_b = (const float*)d_in[8];
    const float* out_proj_w= (const float*)d_in[9];
    const float* out_proj_b= (const float*)d_in[10];
    const float* ln1_g     = (const float*)d_in[11];
    const float* ln1_b     = (const float*)d_in[12];
    const float* ln2_g     = (const float*)d_in[13];
    const float* ln2_b     = (const float*)d_in[14];
    const float* ff1_w     = (const float*)d_in[15];
    const float* ff1_b     = (const float*)d_in[16];
    const float* ff2_w     = (const float*)d_in[17];
    const float* ff2_b     = (const float*)d_in[18];
    float* out = (float*)d_out;

    bf16* pxHi  = symb(g_xHi);   bf16* pxLo  = symb(g_xLo);
    float* pgi   = symf(g_gi);
    float* phseq = symf(g_hseq);
    float* phpos = symf(g_hpos);
    bf16* phpHi = symb(g_hposHi); bf16* phpLo = symb(g_hposLo);
    float* pqkv  = symf(g_qkv);
    bf16* paoHi = symb(g_attnoHi); bf16* paoLo = symb(g_attnoLo);
    float* poproj= symf(g_oproj);
    float* ph1   = symf(g_h1);
    bf16* ph1Hi = symb(g_h1Hi);  bf16* ph1Lo = symb(g_h1Lo);
    bf16* pffHi = symb(g_ffHi);  bf16* pffLo = symb(g_ffLo);
    float* pff2  = symf(g_ff2);
    float* phattn= symf(g_hattn);
    float* pshort= symf(g_short);
    float* pWT   = symf(g_WT);
    bf16* pwHi  = symb(g_wHi);   bf16* pwLo  = symb(g_wLo);
    bf16* paHi  = symb(g_aHi);   bf16* paLo  = symb(g_aLo);
    bf16* pwihHi= symb(g_wihHi); bf16* pwihLo= symb(g_wihLo);
    bf16* pinpHi= symb(g_inpHi); bf16* pinpLo= symb(g_inpLo);
    bf16* popHi = symb(g_opHi);  bf16* popLo = symb(g_opLo);
    bf16* pf1Hi = symb(g_f1Hi);  bf16* pf1Lo = symb(g_f1Lo);
    bf16* pf2Hi = symb(g_f2Hi);  bf16* pf2Lo = symb(g_f2Lo);

    cudaFuncSetAttribute(gru_all_kernel, cudaFuncAttributeMaxDynamicSharedMemorySize, GRU_SMEM);

    const int totBLD = BLr*DD;

    // weight preprocessing
    transpose_whh<<<(3*DD*DD+255)/256, 256>>>(gru_whh, pWT);
    split_w_kernel<<<(384*DD+255)/256, 256>>>(gru_wih, pwihHi, pwihLo, 384*DD);
    split_w_kernel<<<(384*DD+255)/256, 256>>>(in_proj_w, pinpHi, pinpLo, 384*DD);
    split_w_kernel<<<(DD*DD+255)/256, 256>>>(out_proj_w, popHi, popLo, DD*DD);
    split_w_kernel<<<(512*DD+255)/256, 256>>>(ff1_w, pf1Hi, pf1Lo, 512*DD);
    split_w_kernel<<<(DD*512+255)/256, 256>>>(ff2_w, pf2Hi, pf2Lo, DD*512);
    split_emb_kernel<<<(NPAD*DD+255)/256, 256>>>(item_emb, pwHi, pwLo);

    // embedding gather (bf16 hi/lo)
    embed_hilo_kernel<<<(totBLD+255)/256, 256>>>(seq, item_emb, pxHi, pxLo);

    // gi = x @ Wih^T + bih    (M=BLr, N=384, K=128)
    {
        dim3 grid(384/128, BLr/128);
        hmma_gemm<true,false,false,false><<<grid, 256>>>(pxHi, pxLo, pwihHi, pwihLo,
            gru_bih, pgi, nullptr, nullptr, 384, DD);
    }
    // GRU (writes hseq, hpos fp32 + hpos hi/lo)
    gru_all_kernel<<<BB/GRU_ROWS, DD, GRU_SMEM>>>(pgi, pWT, gru_bhh, pos_emb,
        phseq, phpos, phpHi, phpLo);
    // qkv = hpos @ in_proj^T + b   (N=384, K=128)
    {
        dim3 grid(384/128, BLr/128);
        hmma_gemm<true,false,false,false><<<grid, 256>>>(phpHi, phpLo, pinpHi, pinpLo,
            in_proj_b, pqkv, nullptr, nullptr, 384, DD);
    }
    // attention -> attno hi/lo
    {
        dim3 grid(BB, 2);
        attn_kernel<<<grid, 128>>>(pqkv, paoHi, paoLo);
    }
    // GNN short_u
    gnn_kernel<<<BB, 128>>>(seq, item_emb, pshort);
    // out_proj  (N=128, K=128)
    {
        dim3 grid(1, BLr/128);
        hmma_gemm<true,false,false,false><<<grid, 256>>>(paoHi, paoLo, popHi, popLo,
            out_proj_b, poproj, nullptr, nullptr, DD, DD);
    }
    // ln1 (fp32 + hi/lo)
    ln_kernel<true><<<BLr/8, 256>>>(phpos, poproj, ln1_g, ln1_b, ph1, ph1Hi, ph1Lo, BLr);
    // ff1 (relu, bf16 hi/lo out)  (N=512, K=128)
    {
        dim3 grid(512/128, BLr/128);
        hmma_gemm<true,true,true,false><<<grid, 256>>>(ph1Hi, ph1Lo, pf1Hi, pf1Lo,
            ff1_b, nullptr, pffHi, pffLo, 512, DD);
    }
    // ff2  (N=128, K=512)
    {
        dim3 grid(1, BLr/128);
        hmma_gemm<true,false,false,false><<<grid, 256>>>(pffHi, pffLo, pf2Hi, pf2Lo,
            ff2_b, pff2, nullptr, nullptr, DD, 512);
    }
    // ln2 (fp32 only)
    ln_kernel<false><<<BLr/8, 256>>>(ph1, pff2, ln2_g, ln2_b, phattn, nullptr, nullptr, BLr);
    // pooling -> e_hat hi/lo
    pool_kernel<<<BB, 128>>>(seq, phseq, phattn, pshort, paHi, paLo);
    // logits  (M=2048, N=NPAD tiles, Nc=VO, K=128)
    {
        dim3 grid(NPAD/128, BB/128);
        hmma_gemm<false,false,false,true><<<grid, 256>>>(paHi, paLo, pwHi, pwLo,
            nullptr, out, nullptr, nullptr, VO, DD);
    }
}